// round 1
// baseline (speedup 1.0000x reference)
#include <cuda_runtime.h>
#include <cstdint>

// Problem constants
#define NV   128     // vocab
#define NN   512     // states
#define LL   4096    // tokens
#define GG   32      // CTAs (persistent, co-resident)
#define JC   16      // columns per CTA = NN/GG
#define TPB  256
#define SS   4       // prefetch stages

// smem layout (floats): stages[SS*NN*JC] | uvec[NN] | red[128] | stok[LL ints]
#define SMEM_BYTES ((SS*NN*JC + NN + 128) * 4 + LL * 4)

// Tagged vector buffers: high 32 bits = step tag, low 32 = float bits.
__device__ unsigned long long g_u[2][NN];
__device__ float g_pdot[LL * GG];

__device__ __forceinline__ unsigned long long ldcv_u64(const unsigned long long* p) {
    unsigned long long v;
    asm volatile("ld.global.cv.b64 %0, [%1];" : "=l"(v) : "l"(p));
    return v;
}
__device__ __forceinline__ void stcg_u64(unsigned long long* p, unsigned long long v) {
    asm volatile("st.global.cg.b64 [%0], %1;" :: "l"(p), "l"(v));
}
__device__ __forceinline__ void cpasync16(void* smem_dst, const void* gsrc) {
    unsigned sa = (unsigned)__cvta_generic_to_shared(smem_dst);
    asm volatile("cp.async.cg.shared.global [%0], [%1], 16;" :: "r"(sa), "l"(gsrc));
}

// Reset tags + seed u_0 = start. Must run before walk each launch (kills stale
// tags from the previous graph replay — ABA hazard at the final steps otherwise).
__global__ void init_kernel(const float* __restrict__ start) {
    int j = threadIdx.x;
    if (j < NN) {
        stcg_u64(&g_u[1][j], 0xFFFFFFFF00000000ull);
        unsigned long long v = (unsigned long long)__float_as_uint(start[j]); // tag 0
        stcg_u64(&g_u[0][j], v);
    }
}

__global__ void __launch_bounds__(TPB, 1)
walk_kernel(const int* __restrict__ tokens,
            const float* __restrict__ transfer,
            const float* __restrict__ probs) {
    extern __shared__ float sm[];
    float* stg  = sm;                    // SS stages of [512 rows][16 cols]
    float* uvec = sm + SS * NN * JC;     // full u_{t-1}
    float* red  = uvec + NN;             // 8 warps x 16 cols
    int*   stok = (int*)(red + 128);     // token string

    const int tid = threadIdx.x;
    const int g   = blockIdx.x;
    const int j0  = g * JC;
    const int lane = tid & 31, wid = tid >> 5;
    const int qd = tid & 3, r0 = tid >> 2;   // col-quad, row-group

    for (int i = tid; i < LL; i += TPB) stok[i] = tokens[i];
    __syncthreads();

    // Prologue: prefetch matrix slices for steps 1..SS
    for (int t = 1; t <= SS; ++t) {
        int tok = stok[t - 1];
        const float* base = transfer + (size_t)tok * (NN * NN) + j0;
        float* dst = stg + ((t - 1) % SS) * (NN * JC);
        #pragma unroll
        for (int k = 0; k < 8; ++k) {
            int q = tid + k * TPB;           // 0..2047 16B chunks
            cpasync16(dst + q * 4, base + (size_t)(q >> 2) * NN + (q & 3) * 4);
        }
        asm volatile("cp.async.commit_group;");
    }

    for (int t = 1; t <= LL; ++t) {
        // ---- poll u_{t-1}: flag+data fused in one 8B word -> 1 L2 round trip
        {
            const unsigned wantTag = (unsigned)(t - 1);
            const int par = (t - 1) & 1;
            bool d0 = false, d1 = false;
            while (!(d0 && d1)) {
                if (!d0) {
                    unsigned long long v = ldcv_u64(&g_u[par][tid]);
                    if ((unsigned)(v >> 32) == wantTag) {
                        uvec[tid] = __uint_as_float((unsigned)v); d0 = true;
                    }
                }
                if (!d1) {
                    unsigned long long v = ldcv_u64(&g_u[par][tid + TPB]);
                    if ((unsigned)(v >> 32) == wantTag) {
                        uvec[tid + TPB] = __uint_as_float((unsigned)v); d1 = true;
                    }
                }
            }
        }
        asm volatile("cp.async.wait_group 3;");   // = SS-1: stage for step t ready
        __syncthreads();                          // uvec + stage visible to all

        // ---- GEMV slice: out[j0+c] = sum_i u[i] * T[i][j0+c]
        const float* stgt = stg + ((t - 1) % SS) * (NN * JC);
        float4 acc = make_float4(0.f, 0.f, 0.f, 0.f);
        #pragma unroll
        for (int k = 0; k < 8; ++k) {
            int i = r0 + (k << 6);
            float4 m = reinterpret_cast<const float4*>(stgt)[(i << 2) + qd];
            float u = uvec[i];
            acc.x = fmaf(u, m.x, acc.x); acc.y = fmaf(u, m.y, acc.y);
            acc.z = fmaf(u, m.z, acc.z); acc.w = fmaf(u, m.w, acc.w);
        }
        #pragma unroll
        for (int d = 4; d < 32; d <<= 1) {
            acc.x += __shfl_xor_sync(0xffffffffu, acc.x, d);
            acc.y += __shfl_xor_sync(0xffffffffu, acc.y, d);
            acc.z += __shfl_xor_sync(0xffffffffu, acc.z, d);
            acc.w += __shfl_xor_sync(0xffffffffu, acc.w, d);
        }
        if (lane < 4)
            *reinterpret_cast<float4*>(red + wid * 16 + lane * 4) = acc;

        // ---- partial dot u_{t-1}[slice] . probs[tok] (no one waits on this)
        const int tok = stok[t - 1];
        if (wid == 1) {
            float pp = 0.f;
            if (lane < JC)
                pp = uvec[j0 + lane] * __ldg(&probs[(size_t)tok * NN + j0 + lane]);
            #pragma unroll
            for (int d = 1; d < 32; d <<= 1) pp += __shfl_xor_sync(0xffffffffu, pp, d);
            if (lane == 0) g_pdot[(t - 1) * GG + g] = pp;
        }
        __syncthreads();

        // ---- publish ASAP (before issuing prefetch from these threads)
        if (tid < JC) {
            float v = 0.f;
            #pragma unroll
            for (int w = 0; w < 8; ++w) v += red[w * 16 + tid];
            unsigned long long pv =
                ((unsigned long long)(unsigned)t << 32) |
                (unsigned long long)__float_as_uint(v);
            stcg_u64(&g_u[t & 1][j0 + tid], pv);
        }

        // ---- prefetch step t+SS into the slot we just consumed
        if (t + SS <= LL) {
            int tok2 = stok[t + SS - 1];
            const float* base = transfer + (size_t)tok2 * (NN * NN) + j0;
            float* dst = stg + ((t + SS - 1) % SS) * (NN * JC);
            #pragma unroll
            for (int k = 0; k < 8; ++k) {
                int q = tid + k * TPB;
                cpasync16(dst + q * 4, base + (size_t)(q >> 2) * NN + (q & 3) * 4);
            }
        }
        asm volatile("cp.async.commit_group;");   // empty group ok past the end
    }
}

__global__ void finalize_kernel(const float* __restrict__ finals,
                                float* __restrict__ out, int out_size) {
    __shared__ double sd[TPB];
    const int tid = threadIdx.x;

    // prob factors: d_t = sum_g pdot[t][g]; product in double
    double lp = 1.0;
    for (int t = tid; t < LL; t += TPB) {
        float s = 0.f;
        #pragma unroll
        for (int g2 = 0; g2 < GG; ++g2) s += g_pdot[t * GG + g2];
        lp *= (double)s;
    }
    sd[tid] = lp; __syncthreads();
    for (int d = TPB / 2; d > 0; d >>= 1) {
        if (tid < d) sd[tid] *= sd[tid + d];
        __syncthreads();
    }
    double totprod = sd[0];
    __syncthreads();

    // final u (L even -> parity 0), finals dot, write outputs
    double fp = 0.0;
    for (int j = tid; j < NN; j += TPB) {
        unsigned long long v = g_u[0][j];
        float uv = __uint_as_float((unsigned)v);
        if (j < out_size) out[j] = uv;
        fp += (double)uv * (double)finals[j];
    }
    sd[tid] = fp; __syncthreads();
    for (int d = TPB / 2; d > 0; d >>= 1) {
        if (tid < d) sd[tid] += sd[tid + d];
        __syncthreads();
    }
    if (tid == 0 && out_size > NN) out[NN] = (float)(totprod * sd[0]);
}

extern "C" void kernel_launch(void* const* d_in, const int* in_sizes, int n_in,
                              void* d_out, int out_size) {
    const int*   tokens   = (const int*)d_in[0];
    const float* start    = (const float*)d_in[1];
    const float* transfer = (const float*)d_in[2];
    const float* probs    = (const float*)d_in[3];
    const float* finals   = (const float*)d_in[4];
    float* out = (float*)d_out;

    cudaFuncSetAttribute(walk_kernel,
                         cudaFuncAttributeMaxDynamicSharedMemorySize, SMEM_BYTES);

    init_kernel<<<1, 512>>>(start);
    walk_kernel<<<GG, TPB, SMEM_BYTES>>>(tokens, transfer, probs);
    finalize_kernel<<<1, TPB>>>(finals, out, out_size);
}

// round 3
// speedup vs baseline: 1.0926x; 1.0926x over previous
#include <cuda_runtime.h>
#include <cstdint>

// Problem constants
#define NV   128     // vocab
#define NN   512     // states
#define LL   4096    // tokens
#define GG   32      // CTAs (persistent, co-resident)
#define JC   16      // columns per CTA = NN/GG
#define TPB  256
#define SS   4       // prefetch stages

// smem layout (floats): stages[SS*NN*JC] | uvec[NN] | red[128] | stok[LL ints]
#define SMEM_BYTES ((SS*NN*JC + NN + 128) * 4 + LL * 4)

// Tagged vector buffers: high 32 bits = step tag, low 32 = float bits.
__device__ unsigned long long g_u[2][NN];
__device__ float g_pdot[LL * GG];

// L2-coherent GPU-scope atomics (8B word fuses tag+data: no fence needed).
__device__ __forceinline__ unsigned long long ld_poll(const unsigned long long* p) {
    unsigned long long v;
    asm volatile("ld.relaxed.gpu.global.b64 %0, [%1];" : "=l"(v) : "l"(p));
    return v;
}
__device__ __forceinline__ void st_pub(unsigned long long* p, unsigned long long v) {
    asm volatile("st.relaxed.gpu.global.b64 [%0], %1;" :: "l"(p), "l"(v));
}
__device__ __forceinline__ void cpasync16(void* smem_dst, const void* gsrc) {
    unsigned sa = (unsigned)__cvta_generic_to_shared(smem_dst);
    asm volatile("cp.async.cg.shared.global [%0], [%1], 16;" :: "r"(sa), "l"(gsrc));
}

// Reset tags + seed u_0 = start. Runs before walk each launch (kills stale
// tags from the previous graph replay — ABA hazard at the final steps otherwise).
__global__ void init_kernel(const float* __restrict__ start) {
    int j = threadIdx.x;
    if (j < NN) {
        st_pub(&g_u[1][j], 0xFFFFFFFF00000000ull);
        unsigned long long v = (unsigned long long)__float_as_uint(start[j]); // tag 0
        st_pub(&g_u[0][j], v);
    }
}

__global__ void __launch_bounds__(TPB, 1)
walk_kernel(const int* __restrict__ tokens,
            const float* __restrict__ transfer,
            const float* __restrict__ probs) {
    extern __shared__ float sm[];
    float* stg  = sm;                    // SS stages of [512 rows][16 cols]
    float* uvec = sm + SS * NN * JC;     // full u_{t-1}
    float* red  = uvec + NN;             // 8 warps x 16 cols
    int*   stok = (int*)(red + 128);     // token string

    const int tid = threadIdx.x;
    const int g   = blockIdx.x;
    const int j0  = g * JC;
    const int lane = tid & 31, wid = tid >> 5;
    const int qd = tid & 3, r0 = tid >> 2;   // col-quad, row-group

    for (int i = tid; i < LL; i += TPB) stok[i] = tokens[i];
    __syncthreads();

    // Prologue: prefetch matrix slices for steps 1..SS
    for (int t = 1; t <= SS; ++t) {
        int tok = stok[t - 1];
        const float* base = transfer + (size_t)tok * (NN * NN) + j0;
        float* dst = stg + ((t - 1) % SS) * (NN * JC);
        #pragma unroll
        for (int k = 0; k < 8; ++k) {
            int q = tid + k * TPB;           // 0..2047 16B chunks
            cpasync16(dst + q * 4, base + (size_t)(q >> 2) * NN + (q & 3) * 4);
        }
        asm volatile("cp.async.commit_group;");
    }

    for (int t = 1; t <= LL; ++t) {
        // ---- poll u_{t-1}: flag+data fused in one 8B word -> 1 L2 round trip
        {
            const unsigned wantTag = (unsigned)(t - 1);
            const int par = (t - 1) & 1;
            bool d0 = false, d1 = false;
            while (!(d0 && d1)) {
                if (!d0) {
                    unsigned long long v = ld_poll(&g_u[par][tid]);
                    if ((unsigned)(v >> 32) == wantTag) {
                        uvec[tid] = __uint_as_float((unsigned)v); d0 = true;
                    }
                }
                if (!d1) {
                    unsigned long long v = ld_poll(&g_u[par][tid + TPB]);
                    if ((unsigned)(v >> 32) == wantTag) {
                        uvec[tid + TPB] = __uint_as_float((unsigned)v); d1 = true;
                    }
                }
            }
        }
        asm volatile("cp.async.wait_group 3;");   // = SS-1: stage for step t ready
        __syncthreads();                          // uvec + stage visible to all

        // ---- GEMV slice: out[j0+c] = sum_i u[i] * T[i][j0+c]
        const float* stgt = stg + ((t - 1) % SS) * (NN * JC);
        float4 acc = make_float4(0.f, 0.f, 0.f, 0.f);
        #pragma unroll
        for (int k = 0; k < 8; ++k) {
            int i = r0 + (k << 6);
            float4 m = reinterpret_cast<const float4*>(stgt)[(i << 2) + qd];
            float u = uvec[i];
            acc.x = fmaf(u, m.x, acc.x); acc.y = fmaf(u, m.y, acc.y);
            acc.z = fmaf(u, m.z, acc.z); acc.w = fmaf(u, m.w, acc.w);
        }
        #pragma unroll
        for (int d = 4; d < 32; d <<= 1) {
            acc.x += __shfl_xor_sync(0xffffffffu, acc.x, d);
            acc.y += __shfl_xor_sync(0xffffffffu, acc.y, d);
            acc.z += __shfl_xor_sync(0xffffffffu, acc.z, d);
            acc.w += __shfl_xor_sync(0xffffffffu, acc.w, d);
        }
        if (lane < 4)
            *reinterpret_cast<float4*>(red + wid * 16 + lane * 4) = acc;
        __syncthreads();

        // ---- publish ASAP; emission dot AFTER the store (off the chain)
        if (tid < JC) {
            float v = 0.f;
            #pragma unroll
            for (int w = 0; w < 8; ++w) v += red[w * 16 + tid];
            unsigned long long pv =
                ((unsigned long long)(unsigned)t << 32) |
                (unsigned long long)__float_as_uint(v);
            st_pub(&g_u[t & 1][j0 + tid], pv);

            // emission t (t <= LL-1): prob factor uses u_t . probs[tok_t]
            if (t < LL) {
                int tok = stok[t];
                float pp = v * __ldg(&probs[(size_t)tok * NN + j0 + tid]);
                #pragma unroll
                for (int d = 1; d < JC; d <<= 1)
                    pp += __shfl_xor_sync(0x0000FFFFu, pp, d);
                if (tid == 0) g_pdot[t * GG + g] = pp;
            }
        }

        // ---- prefetch step t+SS into the slot we just consumed
        if (t + SS <= LL) {
            int tok2 = stok[t + SS - 1];
            const float* base = transfer + (size_t)tok2 * (NN * NN) + j0;
            float* dst = stg + ((t + SS - 1) % SS) * (NN * JC);
            #pragma unroll
            for (int k = 0; k < 8; ++k) {
                int q = tid + k * TPB;
                cpasync16(dst + q * 4, base + (size_t)(q >> 2) * NN + (q & 3) * 4);
            }
        }
        asm volatile("cp.async.commit_group;");   // empty group ok past the end
    }
}

__global__ void finalize_kernel(const int* __restrict__ tokens,
                                const float* __restrict__ start,
                                const float* __restrict__ probs,
                                const float* __restrict__ finals,
                                float* __restrict__ out, int out_size) {
    __shared__ double sd[TPB];
    const int tid = threadIdx.x;

    // emission 0: dot(start, probs[tok_0]) — walk only covers t=1..LL-1
    {
        const int tok0 = tokens[0];
        double e = 0.0;
        for (int j = tid; j < NN; j += TPB)
            e += (double)start[j] * (double)probs[(size_t)tok0 * NN + j];
        sd[tid] = e; __syncthreads();
        for (int d = TPB / 2; d > 0; d >>= 1) {
            if (tid < d) sd[tid] += sd[tid + d];
            __syncthreads();
        }
    }
    double e0 = sd[0];
    __syncthreads();

    // prob factors: d_t = sum_g pdot[t][g], t=1..LL-1; product in double
    double lp = (tid == 0) ? e0 : 1.0;
    for (int t = tid; t < LL; t += TPB) {
        if (t == 0) continue;
        float s = 0.f;
        #pragma unroll
        for (int g2 = 0; g2 < GG; ++g2) s += g_pdot[t * GG + g2];
        lp *= (double)s;
    }
    sd[tid] = lp; __syncthreads();
    for (int d = TPB / 2; d > 0; d >>= 1) {
        if (tid < d) sd[tid] *= sd[tid + d];
        __syncthreads();
    }
    double totprod = sd[0];
    __syncthreads();

    // final u (L even -> parity 0), finals dot, write outputs
    double fp = 0.0;
    for (int j = tid; j < NN; j += TPB) {
        unsigned long long v = g_u[0][j];
        float uv = __uint_as_float((unsigned)v);
        if (j < out_size) out[j] = uv;
        fp += (double)uv * (double)finals[j];
    }
    sd[tid] = fp; __syncthreads();
    for (int d = TPB / 2; d > 0; d >>= 1) {
        if (tid < d) sd[tid] += sd[tid + d];
        __syncthreads();
    }
    if (tid == 0 && out_size > NN) out[NN] = (float)(totprod * sd[0]);
}

extern "C" void kernel_launch(void* const* d_in, const int* in_sizes, int n_in,
                              void* d_out, int out_size) {
    const int*   tokens   = (const int*)d_in[0];
    const float* start    = (const float*)d_in[1];
    const float* transfer = (const float*)d_in[2];
    const float* probs    = (const float*)d_in[3];
    const float* finals   = (const float*)d_in[4];
    float* out = (float*)d_out;

    cudaFuncSetAttribute(walk_kernel,
                         cudaFuncAttributeMaxDynamicSharedMemorySize, SMEM_BYTES);

    init_kernel<<<1, 512>>>(start);
    walk_kernel<<<GG, TPB, SMEM_BYTES>>>(tokens, transfer, probs);
    finalize_kernel<<<1, TPB>>>(tokens, start, probs, finals, out, out_size);
}

// round 6
// speedup vs baseline: 1.2204x; 1.1170x over previous
#include <cuda_runtime.h>
#include <cstdint>

// Problem constants
#define NV   128     // vocab
#define NN   512     // states
#define LL   4096    // tokens
#define GG   32      // CTAs (persistent, co-resident)
#define JC   16      // columns per CTA = NN/GG
#define TPB  256

// Tagged vector buffers: high 32 bits = step tag, low 32 = float bits.
__device__ unsigned long long g_u[2][NN];
__device__ float g_pdot[LL * GG];

// L2-coherent GPU-scope atomics (8B word fuses tag+data: no fence needed).
__device__ __forceinline__ unsigned long long ld_poll(const unsigned long long* p) {
    unsigned long long v;
    asm volatile("ld.relaxed.gpu.global.b64 %0, [%1];" : "=l"(v) : "l"(p));
    return v;
}
__device__ __forceinline__ void st_pub(unsigned long long* p, unsigned long long v) {
    asm volatile("st.relaxed.gpu.global.b64 [%0], %1;" :: "l"(p), "l"(v));
}

// Reset tags + seed u_0 = start. Runs before walk each launch (kills stale
// tags from the previous graph replay — ABA hazard otherwise).
__global__ void init_kernel(const float* __restrict__ start) {
    int j = threadIdx.x;
    if (j < NN) {
        st_pub(&g_u[1][j], 0xFFFFFFFF00000000ull);
        unsigned long long v = (unsigned long long)__float_as_uint(start[j]); // tag 0
        st_pub(&g_u[0][j], v);
    }
}

__global__ void __launch_bounds__(TPB, 1)
walk_kernel(const int* __restrict__ tokens,
            const float* __restrict__ transfer,
            const float* __restrict__ probs) {
    __shared__ float uvec[NN];    // full u_{t-1}
    __shared__ float red[128];    // 8 warps x 16 cols
    __shared__ int   stok[LL];

    const int tid = threadIdx.x;
    const int g   = blockIdx.x;
    const int j0  = g * JC;
    const int lane = tid & 31, wid = tid >> 5;
    const int qd = tid & 3, r0 = tid >> 2;   // col-quad, row-group

    for (int i = tid; i < LL; i += TPB) stok[i] = tokens[i];
    __syncthreads();

    // Matrix slice register double-buffer: 8 float4 per thread per step.
    float4 A[8], B[8];

    // Prologue: load matrix for step 1 (token stok[0]) into A.
    {
        const int tok = stok[0];
        const float* b = transfer + (size_t)tok * (NN * NN) + j0 + 4 * qd;
        #pragma unroll
        for (int k = 0; k < 8; ++k)
            A[k] = *reinterpret_cast<const float4*>(b + (size_t)(r0 + 64 * k) * NN);
    }

    // One step: consumes `cur` (matrix for step t), prefetches step t+1 into `nxt`.
    auto body = [&](int t, float4* cur, float4* nxt) {
        // ---- prefetch next matrix + emission probs (data-independent, long flight)
        float pv = 0.f;
        if (t < LL) {
            const int tok2 = stok[t];
            const float* b = transfer + (size_t)tok2 * (NN * NN) + j0 + 4 * qd;
            #pragma unroll
            for (int k = 0; k < 8; ++k)
                nxt[k] = *reinterpret_cast<const float4*>(b + (size_t)(r0 + 64 * k) * NN);
            if (wid == 1 && lane < JC)
                pv = __ldg(&probs[(size_t)tok2 * NN + j0 + lane]);
        }

        // ---- poll u_{t-1}: 3-deep pipelined spin (6 loads in flight)
        {
            const unsigned wantTag = (unsigned)(t - 1);
            const int par = (t - 1) & 1;
            const unsigned long long* p0 = &g_u[par][tid];
            const unsigned long long* p1 = &g_u[par][tid + TPB];
            unsigned long long a0 = ld_poll(p0), a1 = ld_poll(p1);
            unsigned long long b0 = ld_poll(p0), b1 = ld_poll(p1);
            unsigned long long c0 = ld_poll(p0), c1 = ld_poll(p1);
            unsigned long long v0, v1;
            for (;;) {
                if ((unsigned)(a0 >> 32) == wantTag && (unsigned)(a1 >> 32) == wantTag) {
                    v0 = a0; v1 = a1; break;
                }
                a0 = ld_poll(p0); a1 = ld_poll(p1);
                if ((unsigned)(b0 >> 32) == wantTag && (unsigned)(b1 >> 32) == wantTag) {
                    v0 = b0; v1 = b1; break;
                }
                b0 = ld_poll(p0); b1 = ld_poll(p1);
                if ((unsigned)(c0 >> 32) == wantTag && (unsigned)(c1 >> 32) == wantTag) {
                    v0 = c0; v1 = c1; break;
                }
                c0 = ld_poll(p0); c1 = ld_poll(p1);
            }
            uvec[tid]       = __uint_as_float((unsigned)v0);
            uvec[tid + TPB] = __uint_as_float((unsigned)v1);
        }
        __syncthreads();

        // ---- GEMV slice from registers: out[j0+c] = sum_i u[i] * T[i][j0+c]
        float4 acc = make_float4(0.f, 0.f, 0.f, 0.f);
        #pragma unroll
        for (int k = 0; k < 8; ++k) {
            float u = uvec[r0 + (k << 6)];
            acc.x = fmaf(u, cur[k].x, acc.x); acc.y = fmaf(u, cur[k].y, acc.y);
            acc.z = fmaf(u, cur[k].z, acc.z); acc.w = fmaf(u, cur[k].w, acc.w);
        }
        #pragma unroll
        for (int d = 4; d < 32; d <<= 1) {
            acc.x += __shfl_xor_sync(0xffffffffu, acc.x, d);
            acc.y += __shfl_xor_sync(0xffffffffu, acc.y, d);
            acc.z += __shfl_xor_sync(0xffffffffu, acc.z, d);
            acc.w += __shfl_xor_sync(0xffffffffu, acc.w, d);
        }
        if (lane < 4)
            *reinterpret_cast<float4*>(red + wid * 16 + lane * 4) = acc;
        __syncthreads();

        // ---- warp 0: gather + publish. warp 1: gather + emission (parallel).
        if (tid < JC) {
            float v = 0.f;
            #pragma unroll
            for (int w = 0; w < 8; ++w) v += red[w * 16 + tid];
            unsigned long long pvw =
                ((unsigned long long)(unsigned)t << 32) |
                (unsigned long long)__float_as_uint(v);
            st_pub(&g_u[t & 1][j0 + tid], pvw);
        } else if (wid == 1 && lane < JC) {
            float v = 0.f;
            #pragma unroll
            for (int w = 0; w < 8; ++w) v += red[w * 16 + lane];
            if (t < LL) {
                float pp = v * pv;
                #pragma unroll
                for (int d = 1; d < JC; d <<= 1)
                    pp += __shfl_xor_sync(0x0000FFFFu, pp, d);
                if (lane == 0) g_pdot[t * GG + g] = pp;
            }
        }
    };

    #pragma unroll 1
    for (int t = 1; t <= LL; t += 2) {   // LL even
        body(t,     A, B);
        body(t + 1, B, A);
    }
}

__global__ void finalize_kernel(const int* __restrict__ tokens,
                                const float* __restrict__ start,
                                const float* __restrict__ probs,
                                const float* __restrict__ finals,
                                float* __restrict__ out, int out_size) {
    __shared__ double sd[TPB];
    const int tid = threadIdx.x;

    // emission 0: dot(start, probs[tok_0]) — walk covers t=1..LL-1
    {
        const int tok0 = tokens[0];
        double e = 0.0;
        for (int j = tid; j < NN; j += TPB)
            e += (double)start[j] * (double)probs[(size_t)tok0 * NN + j];
        sd[tid] = e; __syncthreads();
        for (int d = TPB / 2; d > 0; d >>= 1) {
            if (tid < d) sd[tid] += sd[tid + d];
            __syncthreads();
        }
    }
    double e0 = sd[0];
    __syncthreads();

    // prob factors: d_t = sum_g pdot[t][g], t=1..LL-1; product in double
    double lp = (tid == 0) ? e0 : 1.0;
    for (int t = tid; t < LL; t += TPB) {
        if (t == 0) continue;
        float s = 0.f;
        #pragma unroll
        for (int g2 = 0; g2 < GG; ++g2) s += g_pdot[t * GG + g2];
        lp *= (double)s;
    }
    sd[tid] = lp; __syncthreads();
    for (int d = TPB / 2; d > 0; d >>= 1) {
        if (tid < d) sd[tid] *= sd[tid + d];
        __syncthreads();
    }
    double totprod = sd[0];
    __syncthreads();

    // final u (LL even -> parity 0), finals dot, write outputs
    double fp = 0.0;
    for (int j = tid; j < NN; j += TPB) {
        unsigned long long v = g_u[0][j];
        float uv = __uint_as_float((unsigned)v);
        if (j < out_size) out[j] = uv;
        fp += (double)uv * (double)finals[j];
    }
    sd[tid] = fp; __syncthreads();
    for (int d = TPB / 2; d > 0; d >>= 1) {
        if (tid < d) sd[tid] += sd[tid + d];
        __syncthreads();
    }
    if (tid == 0 && out_size > NN) out[NN] = (float)(totprod * sd[0]);
}

extern "C" void kernel_launch(void* const* d_in, const int* in_sizes, int n_in,
                              void* d_out, int out_size) {
    const int*   tokens   = (const int*)d_in[0];
    const float* start    = (const float*)d_in[1];
    const float* transfer = (const float*)d_in[2];
    const float* probs    = (const float*)d_in[3];
    const float* finals   = (const float*)d_in[4];
    float* out = (float*)d_out;

    init_kernel<<<1, 512>>>(start);
    walk_kernel<<<GG, TPB>>>(tokens, transfer, probs);
    finalize_kernel<<<1, TPB>>>(tokens, start, probs, finals, out, out_size);
}